// round 16
// baseline (speedup 1.0000x reference)
#include <cuda_runtime.h>
#include <cuda_bf16.h>
#include <cstdint>

// CrossAttentionModel_20684562497797 — FINAL
//
// The reference applies softmax over a size-1 axis: softmax of a single finite
// element is exactly 1.0, and the mean over heads of ones is 1.0. The output
// is ones((2048,2048)) independent of all inputs; the two 2048x4096x4096
// GEMMs, RMSNorms and score reductions are dead code under the output. The
// only mandatory work is writing 16 MiB of 1.0f.
//
// Optimization landscape fully swept (R5-R15): grid-stride STG.128, TMA bulk
// copy, flat 2-store, unroll-8, 256-bit STG.256, grids 512-2048, occupancy
// 10-73%, issue 4-15% -> kernel duration pinned at 5.57-6.40us with L2 ~26%
// in every variant. Floor = ~1.3us mandatory L2-port store time
// (16.7MB / ~6300 B/cyc) + ~4.3us launch/ramp/drain invariant. e2e carries
// +-1.3us run-to-run noise on identical source (R9 vs R14).
//
// This configuration (512 CTAs x 256 threads x 8 static STG.128, exact cover
// of 1M float4, single graph node) achieved the best measured e2e (6.624us).

static constexpr int THREADS = 256;
static constexpr int V4_PER_THREAD = 8;
static constexpr int V4_PER_CTA = THREADS * V4_PER_THREAD;  // 2048 float4 = 32 KiB

__global__ __launch_bounds__(THREADS)
void fill_ones_kernel(float4* __restrict__ out4, int n4,
                      float* __restrict__ out, int n_total) {
    const float4 one4 = make_float4(1.0f, 1.0f, 1.0f, 1.0f);
    int base = blockIdx.x * V4_PER_CTA + threadIdx.x;

    // 8 independent coalesced STG.128s, statically unrolled (front-batched by
    // ptxas). Guards uniformly true for the real shape (n4 = 1M, grid = 512).
    #pragma unroll
    for (int j = 0; j < V4_PER_THREAD; j++) {
        int i = base + j * THREADS;
        if (i < n4) out4[i] = one4;
    }

    // Scalar tail for out_size % 4 != 0 (never hit for 2048x2048); keeps the
    // captured graph a single kernel node for any out_size.
    if (blockIdx.x == 0) {
        int t = n4 * 4 + threadIdx.x;
        if (t < n_total) out[t] = 1.0f;
    }
}

extern "C" void kernel_launch(void* const* d_in, const int* in_sizes, int n_in,
                              void* d_out, int out_size) {
    (void)d_in; (void)in_sizes; (void)n_in;

    float* out = (float*)d_out;
    int n4 = out_size / 4;                               // 1,048,576
    int blocks = (n4 + V4_PER_CTA - 1) / V4_PER_CTA;     // 512
    if (blocks < 1) blocks = 1;

    fill_ones_kernel<<<blocks, THREADS>>>((float4*)out, n4, out, out_size);
}

// round 17
// speedup vs baseline: 1.0638x; 1.0638x over previous
#include <cuda_runtime.h>
#include <cstdint>

// CrossAttentionModel_20684562497797 — FINAL
//
// The reference applies softmax over a size-1 axis: softmax of one finite
// element is exactly 1.0, and the mean over heads of ones is 1.0. The output
// is ones((2048,2048)) independent of all inputs; both 2048x4096x4096 GEMMs,
// the RMSNorms, and the score reduction are dead code under the output. The
// only mandatory work is writing 16 MiB of 1.0f.
//
// Sweep summary (R5-R16): grid-stride STG.128, TMA bulk copy, flat 2-store,
// unroll-8, STG.256, grids 512-2048 -> kernel dur pinned at 5.57-6.40us,
// L2 ~23-26%, issue 4-15%, occ 10-73%. No programmable resource binds. The
// floor is ~1.3us mandatory L2-port store time (16.7MB / ~6300 B/cyc) plus
// ~4.3us fixed launch/ramp. e2e on byte-identical source sampled
// {6.62, 7.94, 16.54}us -> e2e is noise-dominated beyond the kernel floor.
//
// This is the single fastest kernel structure measured (5.568us, R7): one
// wave, 2048 CTAs x 256 threads, exactly two coalesced STG.128 per thread
// (exact cover of 1M float4), tail predicated in, one graph node always.

static constexpr int THREADS = 256;
static constexpr int V4_PER_CTA = THREADS * 2;  // 512 float4 = 8 KiB per CTA

__global__ __launch_bounds__(THREADS)
void fill_ones_kernel(float4* __restrict__ out4, int n4,
                      float* __restrict__ out, int n_total) {
    const float4 one4 = make_float4(1.0f, 1.0f, 1.0f, 1.0f);
    int base = blockIdx.x * V4_PER_CTA + threadIdx.x;

    // Two independent, coalesced 128-bit stores; guards uniformly true for
    // the real shape (n4 = 1M, grid = 2048) and predicated for free.
    int i0 = base;
    int i1 = base + THREADS;
    if (i0 < n4) out4[i0] = one4;
    if (i1 < n4) out4[i1] = one4;

    // Scalar tail for out_size % 4 != 0 (never hit for 2048x2048); keeps the
    // captured graph a single kernel node for any out_size.
    if (blockIdx.x == 0) {
        int t = n4 * 4 + threadIdx.x;
        if (t < n_total) out[t] = 1.0f;
    }
}

extern "C" void kernel_launch(void* const* d_in, const int* in_sizes, int n_in,
                              void* d_out, int out_size) {
    (void)d_in; (void)in_sizes; (void)n_in;

    float* out = (float*)d_out;
    int n4 = out_size / 4;                               // 1,048,576
    int blocks = (n4 + V4_PER_CTA - 1) / V4_PER_CTA;     // 2048
    if (blocks < 1) blocks = 1;

    fill_ones_kernel<<<blocks, THREADS>>>((float4*)out, n4, out, out_size);
}